// round 5
// baseline (speedup 1.0000x reference)
#include <cuda_runtime.h>
#include <cuda_fp16.h>
#include <math.h>
#include <stdint.h>

#define BATCH 8
#define SEQ   4096
#define HID   256
#define NF    6

// Precombined per-batch weights, TRANSPOSED to [b][n][h], fp16 hi/lo split.
__device__ __half g_Bhi[BATCH * HID * HID];   // 1 MB
__device__ __half g_Blo[BATCH * HID * HID];   // 1 MB
// x pre-converted to fp16
__device__ __half g_Ah[BATCH * SEQ * HID];    // 16 MB

// ===========================================================================
// Helpers
// ===========================================================================
__device__ __forceinline__ uint32_t smem_u32(const void* p) {
    uint32_t a;
    asm("{ .reg .u64 t; cvta.to.shared.u64 t, %1; cvt.u32.u64 %0, t; }" : "=r"(a) : "l"(p));
    return a;
}
__device__ __forceinline__ void cp_async16(uint32_t dst, const void* src) {
    asm volatile("cp.async.ca.shared.global [%0], [%1], 16;" :: "r"(dst), "l"(src));
}
#define CP_COMMIT() asm volatile("cp.async.commit_group;" ::: "memory")
#define CP_WAIT0()  asm volatile("cp.async.wait_group 0;" ::: "memory")

__device__ __forceinline__ void ldmx4(uint32_t a, uint32_t r[4]) {
    asm volatile("ldmatrix.sync.aligned.m8n8.x4.shared.b16 {%0,%1,%2,%3}, [%4];"
                 : "=r"(r[0]), "=r"(r[1]), "=r"(r[2]), "=r"(r[3]) : "r"(a));
}
__device__ __forceinline__ void ldmx2(uint32_t a, uint32_t r[2]) {
    asm volatile("ldmatrix.sync.aligned.m8n8.x2.shared.b16 {%0,%1}, [%2];"
                 : "=r"(r[0]), "=r"(r[1]) : "r"(a));
}
__device__ __forceinline__ void mma16816(float c[4], const uint32_t a[4], const uint32_t b[2]) {
    asm volatile(
        "mma.sync.aligned.m16n8k16.row.col.f32.f16.f16.f32 "
        "{%0,%1,%2,%3},{%4,%5,%6,%7},{%8,%9},{%0,%1,%2,%3};"
        : "+f"(c[0]), "+f"(c[1]), "+f"(c[2]), "+f"(c[3])
        : "r"(a[0]), "r"(a[1]), "r"(a[2]), "r"(a[3]), "r"(b[0]), "r"(b[1]));
}

// Swizzled byte offset inside a [128 rows][64 fp16] tile (128B rows, XOR swizzle)
__device__ __forceinline__ uint32_t sw_off(int r, int k) {
    int c = k >> 3;
    return (uint32_t)((r << 7) + ((c ^ (r & 7)) << 4) + ((k & 7) << 1));
}

// ===========================================================================
// Kernel 0: convert x -> fp16 (streaming).
// ===========================================================================
__global__ __launch_bounds__(256) void convert_A_kernel(
    const float* __restrict__ X, __half* __restrict__ Ah)
{
    size_t i = ((size_t)blockIdx.x * 256 + threadIdx.x) * 4;
    float4 v = *(const float4*)&X[i];
    __half2 h01 = __floats2half2_rn(v.x, v.y);
    __half2 h23 = __floats2half2_rn(v.z, v.w);
    uint2 o; o.x = *(uint32_t*)&h01; o.y = *(uint32_t*)&h23;
    *(uint2*)&Ah[i] = o;
}

// ===========================================================================
// Kernel 1: build combined weights, transposed + fp16-split.
//   M_b[h][k] = sum_f W[f][h][k] * sin(freq_f * t_b + phase[f][k])
//   g_Bhi[b][n][h] = fp16_hi(M_b[h][n]),  g_Blo = fp16 residual
// ===========================================================================
__global__ __launch_bounds__(256) void build_M_kernel(
    const float* __restrict__ W,      // [F, H, H]
    const float* __restrict__ phase,  // [F, H]
    const float* __restrict__ t)      // [B, 1]
{
    __shared__ __half s_hi[32][HID];
    __shared__ __half s_lo[32][HID];

    const int b  = blockIdx.y;
    const int h0 = blockIdx.x * 32;
    const int k  = threadIdx.x;
    const float tb = t[b];
    const float freqs[NF] = {1.f, 2.f, 4.f, 8.f, 7.f, 5.f};
    float res[NF];
#pragma unroll
    for (int f = 0; f < NF; f++) res[f] = sinf(freqs[f] * tb + phase[f * HID + k]);

    for (int hl = 0; hl < 32; hl++) {
        float acc = 0.f;
#pragma unroll
        for (int f = 0; f < NF; f++)
            acc = fmaf(W[((size_t)f * HID + h0 + hl) * HID + k], res[f], acc);
        __half hi = __float2half_rn(acc);
        s_hi[hl][k] = hi;
        s_lo[hl][k] = __float2half_rn(acc - __half2float(hi));
    }
    __syncthreads();

    const int n = k;
    __half* dhi = &g_Bhi[((size_t)b * HID + n) * HID + h0];
    __half* dlo = &g_Blo[((size_t)b * HID + n) * HID + h0];
#pragma unroll
    for (int i0 = 0; i0 < 32; i0 += 8) {
        __half th[8], tl[8];
#pragma unroll
        for (int j = 0; j < 8; j++) { th[j] = s_hi[i0 + j][n]; tl[j] = s_lo[i0 + j][n]; }
        *(uint4*)&dhi[i0] = *(uint4*)th;
        *(uint4*)&dlo[i0] = *(uint4*)tl;
    }
}

// ===========================================================================
// Kernel 2: mma.sync GEMM.  CTA: 128 rows x 128 cols, K=256 in 4 chunks of 64.
//   D = Ah*Bhi + Ah*Blo  (fp16 operands, fp32 accum; x quantization ~2^-12)
// All operands via cp.async, double-buffered 48KB stages -> 2 CTAs/SM.
// ===========================================================================
#define OFF_AH    0
#define OFF_BHI   16384
#define OFF_BLO   32768
#define ST_STRIDE 49152
#define SMEM_TOTAL (2 * ST_STRIDE)   // 96 KB

__global__ __launch_bounds__(256, 2) void gemm_kernel(
    const __half* __restrict__ Ag,  // [B, SEQ, HID] fp16
    float* __restrict__ Y)          // [B, SEQ, HID]
{
    extern __shared__ char smem[];
    const uint32_t sb = smem_u32(smem);
    const int tid  = threadIdx.x;
    const int wid  = tid >> 5;
    const int lane = tid & 31;
    const int b    = blockIdx.z;
    const int row0 = blockIdx.y * 128;
    const int col0 = blockIdx.x * 128;

    const int wm = (wid & 1) * 64;   // warp tile: 64 rows x 32 cols
    const int wn = (wid >> 1) * 32;

    const __half* A  = Ag    + ((size_t)b * SEQ + row0) * HID;
    const __half* Bh = g_Bhi + ((size_t)b * HID + col0) * HID;
    const __half* Bl = g_Blo + ((size_t)b * HID + col0) * HID;

    float acc[4][4][4];
#pragma unroll
    for (int i = 0; i < 4; i++)
#pragma unroll
        for (int j = 0; j < 4; j++)
#pragma unroll
            for (int q = 0; q < 4; q++) acc[i][j][q] = 0.f;

    // A/B chunk loader: 128 rows x 64 halves each panel, 16B per cp.async
    const int lr = tid >> 3;        // 0..31 (row group base), 4 iters of +32
    const int lc = tid & 7;         // 0..7  (16B column)
    const uint32_t swb = (uint32_t)((lr << 7) + ((lc ^ (lr & 7)) << 4));

#define LOAD_CHUNK(dstoff, kk)                                                  \
    do {                                                                        \
        _Pragma("unroll")                                                       \
        for (int i = 0; i < 4; i++) {                                           \
            int r = lr + i * 32;                                                \
            uint32_t o = (uint32_t)((r << 7) + ((lc ^ (r & 7)) << 4));          \
            size_t g = (size_t)r * HID + (kk) + lc * 8;                         \
            cp_async16(sb + (dstoff) + OFF_AH  + o, &A[g]);                     \
            cp_async16(sb + (dstoff) + OFF_BHI + o, &Bh[g]);                    \
            cp_async16(sb + (dstoff) + OFF_BLO + o, &Bl[g]);                    \
        }                                                                       \
    } while (0)

    (void)swb;
    LOAD_CHUNK(0, 0);
    CP_COMMIT();
    CP_WAIT0();
    __syncthreads();

    for (int c = 0; c < 4; c++) {
        const uint32_t stoff = (uint32_t)(c & 1) * ST_STRIDE;
        const uint32_t nxoff = (uint32_t)((c + 1) & 1) * ST_STRIDE;

        if (c < 3) {
            LOAD_CHUNK(nxoff, (c + 1) * 64);
            CP_COMMIT();
        }

        // ---- compute: 4 k16 steps
#pragma unroll
        for (int s = 0; s < 4; s++) {
            uint32_t ah[4][4], bh[4][2], bl[4][2];
            const int arow = wm + (lane & 15);
            const int akk  = s * 16 + ((lane >> 4) << 3);
#pragma unroll
            for (int mi = 0; mi < 4; mi++)
                ldmx4(sb + stoff + OFF_AH + sw_off(arow + mi * 16, akk), ah[mi]);
            const int bkk = s * 16 + ((lane >> 3) & 1) * 8;
#pragma unroll
            for (int nj = 0; nj < 4; nj++) {
                uint32_t o = sw_off(wn + nj * 8 + (lane & 7), bkk);
                ldmx2(sb + stoff + OFF_BHI + o, bh[nj]);
                ldmx2(sb + stoff + OFF_BLO + o, bl[nj]);
            }
#pragma unroll
            for (int mi = 0; mi < 4; mi++)
#pragma unroll
                for (int nj = 0; nj < 4; nj++) {
                    mma16816(acc[mi][nj], ah[mi], bh[nj]);
                    mma16816(acc[mi][nj], ah[mi], bl[nj]);
                }
        }

        if (c < 3) CP_WAIT0();
        __syncthreads();
    }

    // ---- epilogue: direct register -> global stores
    float* C = Y + ((size_t)b * SEQ + row0) * HID + col0;
#pragma unroll
    for (int mi = 0; mi < 4; mi++) {
        int r0 = wm + mi * 16 + (lane >> 2);
#pragma unroll
        for (int nj = 0; nj < 4; nj++) {
            int cc = wn + nj * 8 + (lane & 3) * 2;
            *(float2*)&C[(size_t)r0 * HID + cc]       = make_float2(acc[mi][nj][0], acc[mi][nj][1]);
            *(float2*)&C[(size_t)(r0 + 8) * HID + cc] = make_float2(acc[mi][nj][2], acc[mi][nj][3]);
        }
    }
#undef LOAD_CHUNK
}

// ===========================================================================
extern "C" void kernel_launch(void* const* d_in, const int* in_sizes, int n_in,
                              void* d_out, int out_size) {
    const float* x     = (const float*)d_in[0];  // [8, 4096, 256]
    const float* t     = (const float*)d_in[1];  // [8, 1]
    const float* osc   = (const float*)d_in[2];  // [6, 256, 256]
    const float* phase = (const float*)d_in[3];  // [6, 256]
    float* out = (float*)d_out;                  // [8, 4096, 256]
    (void)in_sizes; (void)n_in; (void)out_size;

    cudaFuncSetAttribute(gemm_kernel, cudaFuncAttributeMaxDynamicSharedMemorySize, SMEM_TOTAL);

    __half* ah;
    cudaGetSymbolAddress((void**)&ah, g_Ah);

    convert_A_kernel<<<BATCH * SEQ * HID / 1024, 256>>>(x, ah);
    build_M_kernel<<<dim3(8, BATCH), 256>>>(osc, phase, t);
    gemm_kernel<<<dim3(2, 32, BATCH), 256, SMEM_TOTAL>>>(ah, out);
}

// round 6
// speedup vs baseline: 1.7853x; 1.7853x over previous
#include <cuda_runtime.h>
#include <cuda_fp16.h>
#include <math.h>
#include <stdint.h>

#define BATCH 8
#define SEQ   4096
#define HID   256
#define NF    6

// Precombined per-batch weights, TRANSPOSED to [b][n][h], fp16 hi/lo split.
__device__ __half g_Bhi[BATCH * HID * HID];   // 1 MB
__device__ __half g_Blo[BATCH * HID * HID];   // 1 MB

// ===========================================================================
// Helpers
// ===========================================================================
__device__ __forceinline__ uint32_t smem_u32(const void* p) {
    uint32_t a;
    asm("{ .reg .u64 t; cvta.to.shared.u64 t, %1; cvt.u32.u64 %0, t; }" : "=r"(a) : "l"(p));
    return a;
}
__device__ __forceinline__ void cp_async16(uint32_t dst, const void* src) {
    asm volatile("cp.async.ca.shared.global [%0], [%1], 16;" :: "r"(dst), "l"(src));
}
#define CP_COMMIT() asm volatile("cp.async.commit_group;" ::: "memory")
#define CP_WAIT0()  asm volatile("cp.async.wait_group 0;" ::: "memory")

__device__ __forceinline__ void ldmx4(uint32_t a, uint32_t r[4]) {
    asm volatile("ldmatrix.sync.aligned.m8n8.x4.shared.b16 {%0,%1,%2,%3}, [%4];"
                 : "=r"(r[0]), "=r"(r[1]), "=r"(r[2]), "=r"(r[3]) : "r"(a));
}
__device__ __forceinline__ void ldmx2(uint32_t a, uint32_t r[2]) {
    asm volatile("ldmatrix.sync.aligned.m8n8.x2.shared.b16 {%0,%1}, [%2];"
                 : "=r"(r[0]), "=r"(r[1]) : "r"(a));
}
__device__ __forceinline__ void mma16816(float c[4], const uint32_t a[4], const uint32_t b[2]) {
    asm volatile(
        "mma.sync.aligned.m16n8k16.row.col.f32.f16.f16.f32 "
        "{%0,%1,%2,%3},{%4,%5,%6,%7},{%8,%9},{%0,%1,%2,%3};"
        : "+f"(c[0]), "+f"(c[1]), "+f"(c[2]), "+f"(c[3])
        : "r"(a[0]), "r"(a[1]), "r"(a[2]), "r"(a[3]), "r"(b[0]), "r"(b[1]));
}

// Swizzled byte offset inside a [rows][64 fp16] tile (128B rows, XOR swizzle)
__device__ __forceinline__ uint32_t sw_off(int r, int k) {
    int c = k >> 3;
    return (uint32_t)((r << 7) + ((c ^ (r & 7)) << 4) + ((k & 7) << 1));
}

// ===========================================================================
// Kernel 1: build combined weights, transposed + fp16-split.
// grid (32 h-tiles of 8 rows, 8 batches), 256 threads.
//   g_Bhi[b][n][h] = fp16_hi(M_b[h][n]),  g_Blo = fp16 residual
// ===========================================================================
__global__ __launch_bounds__(256) void build_M_kernel(
    const float* __restrict__ W,      // [F, H, H]
    const float* __restrict__ phase,  // [F, H]
    const float* __restrict__ t)      // [B, 1]
{
    __shared__ __half s_hi[8][HID];
    __shared__ __half s_lo[8][HID];

    const int b  = blockIdx.y;
    const int h0 = blockIdx.x * 8;
    const int k  = threadIdx.x;
    const float tb = t[b];
    const float freqs[NF] = {1.f, 2.f, 4.f, 8.f, 7.f, 5.f};
    float res[NF];
#pragma unroll
    for (int f = 0; f < NF; f++) res[f] = sinf(freqs[f] * tb + phase[f * HID + k]);

#pragma unroll
    for (int hl = 0; hl < 8; hl++) {
        float acc = 0.f;
#pragma unroll
        for (int f = 0; f < NF; f++)
            acc = fmaf(W[((size_t)f * HID + h0 + hl) * HID + k], res[f], acc);
        __half hi = __float2half_rn(acc);
        s_hi[hl][k] = hi;
        s_lo[hl][k] = __float2half_rn(acc - __half2float(hi));
    }
    __syncthreads();

    const int n = k;
    __half th[8], tl[8];
#pragma unroll
    for (int j = 0; j < 8; j++) { th[j] = s_hi[j][n]; tl[j] = s_lo[j][n]; }
    *(uint4*)&g_Bhi[((size_t)b * HID + n) * HID + h0] = *(uint4*)th;
    *(uint4*)&g_Blo[((size_t)b * HID + n) * HID + h0] = *(uint4*)tl;
}

// ===========================================================================
// Kernel 2: mma.sync GEMM, CTA tile 128 rows x 256 cols (FULL N), 512 threads.
// K=256 in 4 chunks of 64, double-buffered. x read once as fp32, converted
// in-register to fp16.   D = A*Bhi + A*Blo   (fp32 accum)
// ===========================================================================
#define OFF_AH    0
#define OFF_BHI   16384
#define OFF_BLO   49152
#define ST_STRIDE 81920
#define SMEM_TOTAL (2 * ST_STRIDE)   // 160 KB

__global__ __launch_bounds__(512, 1) void gemm_kernel(
    const float* __restrict__ X,   // [B, SEQ, HID]
    float* __restrict__ Y)         // [B, SEQ, HID]
{
    extern __shared__ char smem[];
    const uint32_t sb = smem_u32(smem);
    const int tid  = threadIdx.x;
    const int wid  = tid >> 5;
    const int lane = tid & 31;
    const int b    = blockIdx.y;
    const int row0 = blockIdx.x * 128;

    // 16 warps: 2 (m) x 8 (n); warp tile 64 rows x 32 cols
    const int wm = (wid & 1) * 64;
    const int wn = (wid >> 1) * 32;

    const float*  A32 = X + ((size_t)b * SEQ + row0) * HID;
    const __half* Bh  = g_Bhi + (size_t)b * HID * HID;
    const __half* Bl  = g_Blo + (size_t)b * HID * HID;

    float acc[4][4][4];
#pragma unroll
    for (int i = 0; i < 4; i++)
#pragma unroll
        for (int j = 0; j < 4; j++)
#pragma unroll
            for (int q = 0; q < 4; q++) acc[i][j][q] = 0.f;

    // B loader: 256 rows x 64 halves/panel; 512 threads -> 4 rows each per panel
    const int lr = tid >> 3;   // 0..63
    const int lc = tid & 7;    // 16B chunk
    // A loader/converter: thread -> (row, 16-float quarter)
    const int ar = tid >> 2;          // 0..127
    const int aq = (tid & 3) * 16;    // k offset of 16 floats
    const uint32_t ao0 = (uint32_t)((ar << 7) + ((((aq >> 3) + 0) ^ (ar & 7)) << 4));
    const uint32_t ao1 = (uint32_t)((ar << 7) + ((((aq >> 3) + 1) ^ (ar & 7)) << 4));

#define LOAD_B(dstoff, kk)                                                      \
    do {                                                                        \
        _Pragma("unroll")                                                       \
        for (int i = 0; i < 4; i++) {                                           \
            int r = lr + i * 64;                                                \
            uint32_t o = (uint32_t)((r << 7) + ((lc ^ (r & 7)) << 4));          \
            size_t g = (size_t)r * HID + (kk) + lc * 8;                         \
            cp_async16(sb + (dstoff) + OFF_BHI + o, &Bh[g]);                    \
            cp_async16(sb + (dstoff) + OFF_BLO + o, &Bl[g]);                    \
        }                                                                       \
    } while (0)

#define LOAD_A(dstoff, kk)                                                      \
    do {                                                                        \
        float4 v0 = *(const float4*)&A32[(size_t)ar * HID + (kk) + aq + 0];     \
        float4 v1 = *(const float4*)&A32[(size_t)ar * HID + (kk) + aq + 4];     \
        float4 v2 = *(const float4*)&A32[(size_t)ar * HID + (kk) + aq + 8];     \
        float4 v3 = *(const float4*)&A32[(size_t)ar * HID + (kk) + aq + 12];    \
        uint4 p0, p1;                                                           \
        __half2 h;                                                              \
        h = __floats2half2_rn(v0.x, v0.y); p0.x = *(uint32_t*)&h;               \
        h = __floats2half2_rn(v0.z, v0.w); p0.y = *(uint32_t*)&h;               \
        h = __floats2half2_rn(v1.x, v1.y); p0.z = *(uint32_t*)&h;               \
        h = __floats2half2_rn(v1.z, v1.w); p0.w = *(uint32_t*)&h;               \
        h = __floats2half2_rn(v2.x, v2.y); p1.x = *(uint32_t*)&h;               \
        h = __floats2half2_rn(v2.z, v2.w); p1.y = *(uint32_t*)&h;               \
        h = __floats2half2_rn(v3.x, v3.y); p1.z = *(uint32_t*)&h;               \
        h = __floats2half2_rn(v3.z, v3.w); p1.w = *(uint32_t*)&h;               \
        *(uint4*)(smem + (dstoff) + OFF_AH + ao0) = p0;                         \
        *(uint4*)(smem + (dstoff) + OFF_AH + ao1) = p1;                         \
    } while (0)

    // ---- prologue: chunk 0
    LOAD_B(0, 0);
    CP_COMMIT();
    LOAD_A(0, 0);
    CP_WAIT0();
    __syncthreads();

    for (int c = 0; c < 4; c++) {
        const uint32_t stoff = (uint32_t)(c & 1) * ST_STRIDE;
        const uint32_t nxoff = (uint32_t)((c + 1) & 1) * ST_STRIDE;

        if (c < 3) {
            LOAD_B(nxoff, (c + 1) * 64);
            CP_COMMIT();
        }

        // ---- compute: 4 k16 steps on current stage
#pragma unroll
        for (int s = 0; s < 4; s++) {
            uint32_t ah[4][4], bh[4][2], bl[4][2];
            const int arow = wm + (lane & 15);
            const int akk  = s * 16 + ((lane >> 4) << 3);
#pragma unroll
            for (int mi = 0; mi < 4; mi++)
                ldmx4(sb + stoff + OFF_AH + sw_off(arow + mi * 16, akk), ah[mi]);
            const int bkk = s * 16 + ((lane >> 3) & 1) * 8;
#pragma unroll
            for (int nj = 0; nj < 4; nj++) {
                uint32_t o = sw_off(wn + nj * 8 + (lane & 7), bkk);
                ldmx2(sb + stoff + OFF_BHI + o, bh[nj]);
                ldmx2(sb + stoff + OFF_BLO + o, bl[nj]);
            }
#pragma unroll
            for (int mi = 0; mi < 4; mi++)
#pragma unroll
                for (int nj = 0; nj < 4; nj++) {
                    mma16816(acc[mi][nj], ah[mi], bh[nj]);
                    mma16816(acc[mi][nj], ah[mi], bl[nj]);
                }
        }

        if (c < 3) {
            LOAD_A(nxoff, (c + 1) * 64);
            CP_WAIT0();
        }
        __syncthreads();
    }

    // ---- epilogue: direct register -> global stores
    float* C = Y + ((size_t)b * SEQ + row0) * HID;
#pragma unroll
    for (int mi = 0; mi < 4; mi++) {
        int r0 = wm + mi * 16 + (lane >> 2);
#pragma unroll
        for (int nj = 0; nj < 4; nj++) {
            int cc = wn + nj * 8 + (lane & 3) * 2;
            *(float2*)&C[(size_t)r0 * HID + cc]       = make_float2(acc[mi][nj][0], acc[mi][nj][1]);
            *(float2*)&C[(size_t)(r0 + 8) * HID + cc] = make_float2(acc[mi][nj][2], acc[mi][nj][3]);
        }
    }
#undef LOAD_B
#undef LOAD_A
}

// ===========================================================================
extern "C" void kernel_launch(void* const* d_in, const int* in_sizes, int n_in,
                              void* d_out, int out_size) {
    const float* x     = (const float*)d_in[0];  // [8, 4096, 256]
    const float* t     = (const float*)d_in[1];  // [8, 1]
    const float* osc   = (const float*)d_in[2];  // [6, 256, 256]
    const float* phase = (const float*)d_in[3];  // [6, 256]
    float* out = (float*)d_out;                  // [8, 4096, 256]
    (void)in_sizes; (void)n_in; (void)out_size;

    cudaFuncSetAttribute(gemm_kernel, cudaFuncAttributeMaxDynamicSharedMemorySize, SMEM_TOTAL);

    build_M_kernel<<<dim3(32, BATCH), 256>>>(osc, phase, t);
    gemm_kernel<<<dim3(SEQ / 128, BATCH), 512, SMEM_TOTAL>>>(x, out);
}

// round 7
// speedup vs baseline: 2.1106x; 1.1822x over previous
#include <cuda_runtime.h>
#include <cuda_fp16.h>
#include <math.h>
#include <stdint.h>

#define BATCH 8
#define SEQ   4096
#define HID   256
#define NF    6

// Precombined per-batch weights, TRANSPOSED to [b][n][h], fp16.
__device__ __half g_B[BATCH * HID * HID];   // 1 MB

// ===========================================================================
// Helpers
// ===========================================================================
__device__ __forceinline__ uint32_t smem_u32(const void* p) {
    uint32_t a;
    asm("{ .reg .u64 t; cvta.to.shared.u64 t, %1; cvt.u32.u64 %0, t; }" : "=r"(a) : "l"(p));
    return a;
}
__device__ __forceinline__ void cp_async16(uint32_t dst, const void* src) {
    asm volatile("cp.async.ca.shared.global [%0], [%1], 16;" :: "r"(dst), "l"(src));
}
#define CP_COMMIT() asm volatile("cp.async.commit_group;" ::: "memory")
#define CP_WAIT0()  asm volatile("cp.async.wait_group 0;" ::: "memory")
#define CP_WAIT1()  asm volatile("cp.async.wait_group 1;" ::: "memory")

__device__ __forceinline__ void ldmx4(uint32_t a, uint32_t r[4]) {
    asm volatile("ldmatrix.sync.aligned.m8n8.x4.shared.b16 {%0,%1,%2,%3}, [%4];"
                 : "=r"(r[0]), "=r"(r[1]), "=r"(r[2]), "=r"(r[3]) : "r"(a));
}
__device__ __forceinline__ void ldmx2(uint32_t a, uint32_t r[2]) {
    asm volatile("ldmatrix.sync.aligned.m8n8.x2.shared.b16 {%0,%1}, [%2];"
                 : "=r"(r[0]), "=r"(r[1]) : "r"(a));
}
__device__ __forceinline__ void mma16816(float c[4], const uint32_t a[4], const uint32_t b[2]) {
    asm volatile(
        "mma.sync.aligned.m16n8k16.row.col.f32.f16.f16.f32 "
        "{%0,%1,%2,%3},{%4,%5,%6,%7},{%8,%9},{%0,%1,%2,%3};"
        : "+f"(c[0]), "+f"(c[1]), "+f"(c[2]), "+f"(c[3])
        : "r"(a[0]), "r"(a[1]), "r"(a[2]), "r"(a[3]), "r"(b[0]), "r"(b[1]));
}

// Swizzled byte offset inside a [rows][64 fp16] tile (128B rows, XOR swizzle)
__device__ __forceinline__ uint32_t sw_off(int r, int k) {
    int c = k >> 3;
    return (uint32_t)((r << 7) + ((c ^ (r & 7)) << 4) + ((k & 7) << 1));
}

// ===========================================================================
// Kernel 1: build combined weights for ALL batches (W read once).
// grid = 32 blocks (8 h-rows each), 256 threads.
//   M_b[h][n] = sum_f W[f][h][n] * sin(freq_f * t_b + phase[f][n])
//   g_B[b][n][h] = fp16(M_b[h][n])   (transposed)
// ===========================================================================
__global__ __launch_bounds__(256) void build_M_kernel(
    const float* __restrict__ W,      // [F, H, H]
    const float* __restrict__ phase,  // [F, H]
    const float* __restrict__ t)      // [B, 1]
{
    __shared__ __half s_hi[BATCH][8][HID];   // 32 KB

    const int h0 = blockIdx.x * 8;
    const int k  = threadIdx.x;
    const float freqs[NF] = {1.f, 2.f, 4.f, 8.f, 7.f, 5.f};

    float res[BATCH][NF];
#pragma unroll
    for (int b = 0; b < BATCH; b++) {
        float tb = t[b];
#pragma unroll
        for (int f = 0; f < NF; f++)
            res[b][f] = sinf(freqs[f] * tb + phase[f * HID + k]);
    }

#pragma unroll
    for (int hl = 0; hl < 8; hl++) {
        float w[NF];
#pragma unroll
        for (int f = 0; f < NF; f++)
            w[f] = W[((size_t)f * HID + h0 + hl) * HID + k];
#pragma unroll
        for (int b = 0; b < BATCH; b++) {
            float acc = 0.f;
#pragma unroll
            for (int f = 0; f < NF; f++) acc = fmaf(w[f], res[b][f], acc);
            s_hi[b][hl][k] = __float2half_rn(acc);
        }
    }
    __syncthreads();

    const int n = k;
#pragma unroll
    for (int b = 0; b < BATCH; b++) {
        __half th[8];
#pragma unroll
        for (int j = 0; j < 8; j++) th[j] = s_hi[b][j][n];
        *(uint4*)&g_B[((size_t)b * HID + n) * HID + h0] = *(uint4*)th;
    }
}

// ===========================================================================
// Kernel 2: fp16 mma.sync GEMM, CTA tile 128 x 128, 256 threads, 2 CTAs/SM.
// A (128x256) converted fp32->fp16 once into persistent smem (64 KB).
// B streamed in 4 chunks of 64-k (16 KB/stage, double-buffered cp.async).
// ===========================================================================
#define OFF_A      0                  // 4 tiles x 16 KB = 64 KB
#define OFF_B      65536              // 2 stages x 16 KB
#define SMEM_TOTAL (65536 + 32768)    // 96 KB

__global__ __launch_bounds__(256, 2) void gemm_kernel(
    const float* __restrict__ X,   // [B, SEQ, HID]
    float* __restrict__ Y)         // [B, SEQ, HID]
{
    extern __shared__ char smem[];
    const uint32_t sb = smem_u32(smem);
    const int tid  = threadIdx.x;
    const int wid  = tid >> 5;
    const int lane = tid & 31;
    const int b    = blockIdx.z;
    const int row0 = blockIdx.y * 128;
    const int col0 = blockIdx.x * 128;

    // 8 warps: 2 (m) x 4 (n); warp tile 64 rows x 32 cols
    const int wm = (wid & 1) * 64;
    const int wn = (wid >> 1) * 32;

    const float*  A32 = X   + ((size_t)b * SEQ + row0) * HID;
    const __half* Bg  = g_B + ((size_t)b * HID + col0) * HID;

    float acc[4][4][4];
#pragma unroll
    for (int i = 0; i < 4; i++)
#pragma unroll
        for (int j = 0; j < 4; j++)
#pragma unroll
            for (int q = 0; q < 4; q++) acc[i][j][q] = 0.f;

    // B loader: 128 n-rows x 64 k halves; 256 thr -> 4 cp.async each
    const int lr = tid >> 3;   // n-row 0..31 (+32*i)
    const int lc = tid & 7;    // 16B chunk

#define LOAD_B(stage, kk)                                                       \
    do {                                                                        \
        _Pragma("unroll")                                                       \
        for (int i = 0; i < 4; i++) {                                           \
            int r = lr + i * 32;                                                \
            uint32_t o = (uint32_t)((stage) * 16384) +                          \
                         (uint32_t)((r << 7) + ((lc ^ (r & 7)) << 4));          \
            cp_async16(sb + OFF_B + o, &Bg[(size_t)r * HID + (kk) + lc * 8]);   \
        }                                                                       \
    } while (0)

    // ---- prologue: start B chunk 0, then convert the whole A panel
    LOAD_B(0, 0);
    CP_COMMIT();

#pragma unroll
    for (int i = 0; i < 32; i++) {
        int e = i * 256 + tid;
        int r = e >> 6, q = e & 63;          // row, float4 index (k = q*4)
        int k = q * 4;
        float4 v = *(const float4*)&A32[(size_t)r * HID + k];
        __half2 h01 = __floats2half2_rn(v.x, v.y);
        __half2 h23 = __floats2half2_rn(v.z, v.w);
        uint2 p; p.x = *(uint32_t*)&h01; p.y = *(uint32_t*)&h23;
        uint32_t off = (uint32_t)((k >> 6) * 16384) + sw_off(r, k & 63);
        *(uint2*)(smem + OFF_A + off) = p;
    }

#pragma unroll
    for (int c = 0; c < 4; c++) {
        if (c + 1 < 4) { LOAD_B((c + 1) & 1, (c + 1) * 64); CP_COMMIT(); }
        if (c < 3) CP_WAIT1(); else CP_WAIT0();
        __syncthreads();

        const uint32_t aoff = sb + OFF_A + (uint32_t)c * 16384;
        const uint32_t boff = sb + OFF_B + (uint32_t)(c & 1) * 16384;

#pragma unroll
        for (int s = 0; s < 4; s++) {
            uint32_t ah[4][4], bh[4][2];
            const int arow = wm + (lane & 15);
            const int akk  = s * 16 + ((lane >> 4) << 3);
#pragma unroll
            for (int mi = 0; mi < 4; mi++)
                ldmx4(aoff + sw_off(arow + mi * 16, akk), ah[mi]);
            const int bkk = s * 16 + ((lane >> 3) & 1) * 8;
#pragma unroll
            for (int nj = 0; nj < 4; nj++)
                ldmx2(boff + sw_off(wn + nj * 8 + (lane & 7), bkk), bh[nj]);
#pragma unroll
            for (int mi = 0; mi < 4; mi++)
#pragma unroll
                for (int nj = 0; nj < 4; nj++)
                    mma16816(acc[mi][nj], ah[mi], bh[nj]);
        }
        __syncthreads();
    }

    // ---- epilogue: direct register -> global stores
    float* C = Y + ((size_t)b * SEQ + row0) * HID + col0;
#pragma unroll
    for (int mi = 0; mi < 4; mi++) {
        int r0 = wm + mi * 16 + (lane >> 2);
#pragma unroll
        for (int nj = 0; nj < 4; nj++) {
            int cc = wn + nj * 8 + (lane & 3) * 2;
            *(float2*)&C[(size_t)r0 * HID + cc]       = make_float2(acc[mi][nj][0], acc[mi][nj][1]);
            *(float2*)&C[(size_t)(r0 + 8) * HID + cc] = make_float2(acc[mi][nj][2], acc[mi][nj][3]);
        }
    }
#undef LOAD_B
}

// ===========================================================================
extern "C" void kernel_launch(void* const* d_in, const int* in_sizes, int n_in,
                              void* d_out, int out_size) {
    const float* x     = (const float*)d_in[0];  // [8, 4096, 256]
    const float* t     = (const float*)d_in[1];  // [8, 1]
    const float* osc   = (const float*)d_in[2];  // [6, 256, 256]
    const float* phase = (const float*)d_in[3];  // [6, 256]
    float* out = (float*)d_out;                  // [8, 4096, 256]
    (void)in_sizes; (void)n_in; (void)out_size;

    cudaFuncSetAttribute(gemm_kernel, cudaFuncAttributeMaxDynamicSharedMemorySize, SMEM_TOTAL);

    build_M_kernel<<<32, 256>>>(osc, phase, t);
    gemm_kernel<<<dim3(2, 32, BATCH), 256, SMEM_TOTAL>>>(x, out);
}